// round 4
// baseline (speedup 1.0000x reference)
#include <cuda_runtime.h>
#include <math.h>

// ---------------- constants ----------------
#define C_CURV 0.05f
#define SQC    0.22360679774997896f          // sqrt(0.05)
#define MAXNORM (0.996f / 0.22360679774997896f)  // (1-4e-3)/sqrt(c)
#define MINN   1e-15f

#define BS   32
#define CIN  64
#define COUT 128
#define HW   64
#define NPIX 4096      // 64*64
#define HP   66        // padded
#define TSTRIDE 68     // smem tile row stride (padding)

#define NT   512       // threads per block (main kernel)
#define CPB  4         // couts per block

// scratch (allocation-free rule: __device__ globals)
__device__ float g_sc[BS * CIN];   // logmap0 scale per (b,cin)
__device__ float g_bh[COUT];       // expmap0(bias)

// ---------------- kernel A: logmap0 scales ----------------
__global__ void scale_kernel(const float* __restrict__ x) {
    int bc = blockIdx.x;                       // 0..2047
    const float* xp = x + (size_t)bc * NPIX;
    float s = 0.f;
    for (int i = threadIdx.x; i < NPIX; i += 256) { float v = xp[i]; s += v * v; }
    __shared__ float red[8];
    #pragma unroll
    for (int o = 16; o; o >>= 1) s += __shfl_xor_sync(0xffffffffu, s, o);
    if ((threadIdx.x & 31) == 0) red[threadIdx.x >> 5] = s;
    __syncthreads();
    if (threadIdx.x == 0) {
        float tot = 0.f;
        #pragma unroll
        for (int w = 0; w < 8; w++) tot += red[w];
        float n = fmaxf(sqrtf(tot), MINN);
        float a = fminf(SQC * n, 1.f - 1e-7f);
        float art = 0.5f * (log1pf(a) - log1pf(-a));
        g_sc[bc] = art / (SQC * n);
    }
}

// ---------------- kernel B: hyperbolic bias ----------------
__global__ void bias_kernel(const float* __restrict__ bias) {
    __shared__ float red[4];
    int t = threadIdx.x;                       // 128 threads
    float v = bias[t];
    float s = v * v;
    #pragma unroll
    for (int o = 16; o; o >>= 1) s += __shfl_xor_sync(0xffffffffu, s, o);
    if ((t & 31) == 0) red[t >> 5] = s;
    __syncthreads();
    float tot = red[0] + red[1] + red[2] + red[3];
    float n = fmaxf(sqrtf(tot), MINN);
    g_bh[t] = tanhf(SQC * n) * v / (SQC * n);
}

// ---------------- block reduction of 8 scalars ----------------
__device__ __forceinline__ void block_reduce8(float part[8], float (*red)[16],
                                              float* res, int t) {
    #pragma unroll
    for (int q = 0; q < 8; q++) {
        #pragma unroll
        for (int o = 16; o; o >>= 1)
            part[q] += __shfl_xor_sync(0xffffffffu, part[q], o);
    }
    if ((t & 31) == 0) {
        int wd = t >> 5;
        #pragma unroll
        for (int q = 0; q < 8; q++) red[q][wd] = part[q];
    }
    __syncthreads();
    if (t < 32) {
        #pragma unroll
        for (int q = 0; q < 8; q++) {
            float val = (t < 16) ? red[q][t] : 0.f;
            #pragma unroll
            for (int o = 8; o; o >>= 1)
                val += __shfl_xor_sync(0xffffffffu, val, o);
            if (t == 0) res[q] = val;
        }
    }
    __syncthreads();
}

// ---------------- main kernel ----------------
__global__ __launch_bounds__(NT, 1)
void hypconv_kernel(const float* __restrict__ x, const float* __restrict__ w,
                    float* __restrict__ out) {
    __shared__ float up[HP * TSTRIDE];         // 66x68 scaled padded tile
    __shared__ float ws[CPB * CIN * 9];        // weights for this block's 4 couts
    __shared__ float red[8][16];
    __shared__ float res[8];

    int b   = blockIdx.y;                      // 0..31
    int cog = blockIdx.x;                      // 0..31 (cout group)
    int t   = threadIdx.x;
    int r   = t >> 3;                          // output row 0..63
    int cb  = (t & 7) * 8;                     // output col base

    // preload weights: 4 couts x 64 ch x 9
    for (int i = t; i < CPB * CIN * 9; i += NT) {
        int cc = i / (CIN * 9);
        int rem = i - cc * (CIN * 9);
        ws[i] = w[(cog * CPB + cc) * (CIN * 9) + rem];
    }

    float acc[CPB][8];
    float x2[CPB];
    #pragma unroll
    for (int cc = 0; cc < CPB; cc++) {
        x2[cc] = 0.f;
        #pragma unroll
        for (int i = 0; i < 8; i++) acc[cc][i] = 0.f;
    }

    const float* xb = x + (size_t)b * CIN * NPIX;

    for (int j = 0; j < CIN; j++) {
        float scj = g_sc[b * CIN + j];
        __syncthreads();                       // tile free; covers ws preload on j==0
        // stage scaled+padded tile
        const float* xc = xb + (size_t)j * NPIX;
        for (int i = t; i < HP * HP; i += NT) {
            int pr = i / HP, pc = i - pr * HP;
            float v = 0.f;
            if (pr >= 1 && pr <= HW && pc >= 1 && pc <= HW)
                v = xc[(pr - 1) * HW + (pc - 1)] * scj;
            up[pr * TSTRIDE + pc] = v;
        }
        __syncthreads();

        // register-block the 3x10 input patch (shared by all 4 couts)
        float u0[10], u1[10], u2[10];
        {
            const float* p0 = &up[r * TSTRIDE + cb];
            #pragma unroll
            for (int i = 0; i < 10; i++) {
                u0[i] = p0[i];
                u1[i] = p0[TSTRIDE + i];
                u2[i] = p0[2 * TSTRIDE + i];
            }
        }

        float v[CPB][8];
        float part[8];
        #pragma unroll
        for (int cc = 0; cc < CPB; cc++) {
            const float* wp = &ws[cc * (CIN * 9) + j * 9];
            float w0 = wp[0], w1 = wp[1], w2 = wp[2];
            float w3 = wp[3], w4 = wp[4], w5 = wp[5];
            float w6 = wp[6], w7 = wp[7], w8 = wp[8];
            float sv2 = 0.f, sav = 0.f;
            #pragma unroll
            for (int i = 0; i < 8; i++) {
                float vv = u0[i] * w0 + u0[i + 1] * w1 + u0[i + 2] * w2
                         + u1[i] * w3 + u1[i + 1] * w4 + u1[i + 2] * w5
                         + u2[i] * w6 + u2[i + 1] * w7 + u2[i + 2] * w8;
                v[cc][i] = vv;
                sv2 += vv * vv;
                sav += acc[cc][i] * vv;
            }
            part[cc * 2]     = sv2;
            part[cc * 2 + 1] = sav;
        }

        block_reduce8(part, red, res, t);

        // mobius update per cout (scalar math is uniform across the block)
        #pragma unroll
        for (int cc = 0; cc < CPB; cc++) {
            float sv2 = res[cc * 2], sav = res[cc * 2 + 1];
            float nv  = sqrtf(sv2);
            float un  = fmaxf(nv, MINN);
            float th  = tanhf(SQC * un);
            float m   = fminf(th, 0.996f);           // fold project(t)
            float gam = m / (SQC * un);
            float y2  = gam * gam * sv2;
            float xy  = gam * sav;
            float A   = 1.f + 2.f * C_CURV * xy + C_CURV * y2;
            float B   = 1.f - C_CURV * x2[cc];
            float den = fmaxf(1.f + 2.f * C_CURV * xy
                              + C_CURV * C_CURV * x2[cc] * y2, MINN);
            float rden = 1.f / den;
            float n2 = (A * A * x2[cc] + 2.f * A * B * xy + B * B * y2) * rden * rden;
            float n  = fmaxf(sqrtf(n2), MINN);
            float ps = (n > MAXNORM) ? (MAXNORM / n) : 1.f;
            float ka = A * rden * ps;
            float kv = B * gam * rden * ps;
            #pragma unroll
            for (int i = 0; i < 8; i++)
                acc[cc][i] = ka * acc[cc][i] + kv * v[cc][i];
            float nn = fminf(n, MAXNORM);
            x2[cc] = nn * nn;
        }
    }

    // ---- bias step: y spatially constant -> only need sum(acc) ----
    {
        float part[8];
        #pragma unroll
        for (int cc = 0; cc < CPB; cc++) {
            float s = 0.f;
            #pragma unroll
            for (int i = 0; i < 8; i++) s += acc[cc][i];
            part[cc] = s;
        }
        #pragma unroll
        for (int cc = CPB; cc < 8; cc++) part[cc] = 0.f;

        __syncthreads();
        block_reduce8(part, red, res, t);

        #pragma unroll
        for (int cc = 0; cc < CPB; cc++) {
            int co = cog * CPB + cc;
            float bh = g_bh[co];
            float sa = res[cc];
            float y2 = (float)NPIX * bh * bh;
            float xy = bh * sa;
            float A   = 1.f + 2.f * C_CURV * xy + C_CURV * y2;
            float B   = 1.f - C_CURV * x2[cc];
            float den = fmaxf(1.f + 2.f * C_CURV * xy
                              + C_CURV * C_CURV * x2[cc] * y2, MINN);
            float rden = 1.f / den;
            float n2 = (A * A * x2[cc] + 2.f * A * B * xy + B * B * y2) * rden * rden;
            float n  = fmaxf(sqrtf(n2), MINN);
            float ps = (n > MAXNORM) ? (MAXNORM / n) : 1.f;
            float ka = A * rden * ps;
            float kb = B * bh * rden * ps;

            float o4a[4], o4b[4];
            #pragma unroll
            for (int i = 0; i < 4; i++) o4a[i] = ka * acc[cc][i] + kb;
            #pragma unroll
            for (int i = 0; i < 4; i++) o4b[i] = ka * acc[cc][4 + i] + kb;

            float* op = out + (((size_t)b * COUT + co) * HW + r) * HW + cb;
            *reinterpret_cast<float4*>(op)     = make_float4(o4a[0], o4a[1], o4a[2], o4a[3]);
            *reinterpret_cast<float4*>(op + 4) = make_float4(o4b[0], o4b[1], o4b[2], o4b[3]);
        }
    }
}

// ---------------- launch ----------------
extern "C" void kernel_launch(void* const* d_in, const int* in_sizes, int n_in,
                              void* d_out, int out_size) {
    const float* x    = (const float*)d_in[0];
    const float* wgt  = (const float*)d_in[1];
    const float* bias = (const float*)d_in[2];
    float* out = (float*)d_out;

    scale_kernel<<<BS * CIN, 256>>>(x);
    bias_kernel<<<1, COUT>>>(bias);
    dim3 grid(COUT / CPB, BS);   // (32, 32)
    hypconv_kernel<<<grid, NT>>>(x, wgt, out);
}

// round 5
// speedup vs baseline: 1.5871x; 1.5871x over previous
#include <cuda_runtime.h>
#include <math.h>

// ---------------- constants ----------------
#define C_CURV 0.05f
#define SQC    0.22360679774997896f              // sqrt(0.05)
#define MAXNORM (0.996f / 0.22360679774997896f)  // (1-4e-3)/sqrt(c)
#define MINN   1e-15f

#define BS   32
#define CIN  64
#define COUT 128
#define HW   64
#define NPIX 4096      // 64*64
#define HPAD 66        // padded rows (0 and 65 are halo)
#define T    68        // smem tile row stride (floats); 2-way LDS conflicts, 16B-alignable
#define OCOL 4         // interior column base (input col y -> smem col y+4); left halo col 3

#define NT   512       // threads per block (main kernel)
#define CPB  4         // couts per block
#define TILE (HPAD * T)   // 4488 floats

// scratch (allocation-free rule: __device__ globals)
__device__ float g_sc[BS * CIN];   // logmap0 scale per (b,cin)
__device__ float g_bh[COUT];       // expmap0(bias)

// ---------------- kernel A: logmap0 scales ----------------
__global__ void scale_kernel(const float* __restrict__ x) {
    int bc = blockIdx.x;                       // 0..2047
    const float* xp = x + (size_t)bc * NPIX;
    float s = 0.f;
    for (int i = threadIdx.x; i < NPIX; i += 256) { float v = xp[i]; s += v * v; }
    __shared__ float red[8];
    #pragma unroll
    for (int o = 16; o; o >>= 1) s += __shfl_xor_sync(0xffffffffu, s, o);
    if ((threadIdx.x & 31) == 0) red[threadIdx.x >> 5] = s;
    __syncthreads();
    if (threadIdx.x == 0) {
        float tot = 0.f;
        #pragma unroll
        for (int w = 0; w < 8; w++) tot += red[w];
        float n = fmaxf(sqrtf(tot), MINN);
        float a = fminf(SQC * n, 1.f - 1e-7f);
        float art = 0.5f * (log1pf(a) - log1pf(-a));
        g_sc[bc] = art / (SQC * n);
    }
}

// ---------------- kernel B: hyperbolic bias ----------------
__global__ void bias_kernel(const float* __restrict__ bias) {
    __shared__ float red[4];
    int t = threadIdx.x;                       // 128 threads
    float v = bias[t];
    float s = v * v;
    #pragma unroll
    for (int o = 16; o; o >>= 1) s += __shfl_xor_sync(0xffffffffu, s, o);
    if ((t & 31) == 0) red[t >> 5] = s;
    __syncthreads();
    float tot = red[0] + red[1] + red[2] + red[3];
    float n = fmaxf(sqrtf(tot), MINN);
    g_bh[t] = tanhf(SQC * n) * v / (SQC * n);
}

// ---------------- main kernel ----------------
__global__ __launch_bounds__(NT, 1)
void hypconv_kernel(const float* __restrict__ x, const float* __restrict__ w,
                    float* __restrict__ out) {
    __shared__ float buf[2][TILE];             // double-buffered scaled padded tiles
    __shared__ float ws[CPB * CIN * 9];        // weights for this block's 4 couts
    __shared__ float sc_s[CIN];                // logmap scales for this batch
    __shared__ float red[8][16];
    __shared__ float res[8];

    int b   = blockIdx.y;                      // 0..31
    int cog = blockIdx.x;                      // 0..31 (cout group)
    int t   = threadIdx.x;
    int r   = t >> 3;                          // output row 0..63
    int cb  = (t & 7) * 8;                     // output col base
    int lane = t & 31;
    int wid  = t >> 5;

    // staging geometry (2 float4 per thread per tile)
    int srow = t >> 4;                         // 0..31
    int scol = (t & 15) * 4;                   // 0..60
    int g0 = srow * HW + scol;                 // global float offset (row<32)
    int g1 = g0 + 32 * HW;                     // rows 32..63
    int d0 = (srow + 1) * T + OCOL + scol;     // smem float offset (16B aligned)
    int d1 = d0 + 32 * T;

    // zero both buffers ONCE (halos stay zero forever; interior overwritten each step)
    for (int i = t; i < 2 * TILE; i += NT) ((float*)buf)[i] = 0.f;
    // preload weights: 4 couts x 64 ch x 9
    for (int i = t; i < CPB * CIN * 9; i += NT) {
        int cc = i / (CIN * 9);
        int rem = i - cc * (CIN * 9);
        ws[i] = w[(cog * CPB + cc) * (CIN * 9) + rem];
    }
    if (t < CIN) sc_s[t] = g_sc[b * CIN + t];
    __syncthreads();

    const float* xb = x + (size_t)b * CIN * NPIX;

    // stage tile 0
    {
        float s0 = sc_s[0];
        float4 a0 = *reinterpret_cast<const float4*>(xb + g0);
        float4 a1 = *reinterpret_cast<const float4*>(xb + g1);
        float* B = buf[0];
        *reinterpret_cast<float4*>(B + d0) =
            make_float4(a0.x * s0, a0.y * s0, a0.z * s0, a0.w * s0);
        *reinterpret_cast<float4*>(B + d1) =
            make_float4(a1.x * s0, a1.y * s0, a1.z * s0, a1.w * s0);
    }
    __syncthreads();

    float acc[CPB][8];
    float x2[CPB];
    #pragma unroll
    for (int cc = 0; cc < CPB; cc++) {
        x2[cc] = 0.f;
        #pragma unroll
        for (int i = 0; i < 8; i++) acc[cc][i] = 0.f;
    }

    for (int j = 0; j < CIN; j++) {
        const float* A = buf[j & 1];

        // prefetch next channel's tile into registers (hidden under the conv)
        float4 pf0, pf1;
        if (j < CIN - 1) {
            const float* xn = xb + (size_t)(j + 1) * NPIX;
            pf0 = *reinterpret_cast<const float4*>(xn + g0);
            pf1 = *reinterpret_cast<const float4*>(xn + g1);
        }

        // register-block the 3x10 input patch (shared by all 4 couts)
        float u0[10], u1[10], u2[10];
        {
            const float* p0 = A + r * T + 3 + cb;   // left halo at col 3
            #pragma unroll
            for (int i = 0; i < 10; i++) {
                u0[i] = p0[i];
                u1[i] = p0[T + i];
                u2[i] = p0[2 * T + i];
            }
        }
        // right-halo patch: col 68 doesn't exist in the T=68 row; value must be 0
        if (cb == 56) { u0[9] = 0.f; u1[9] = 0.f; u2[9] = 0.f; }

        float v[CPB][8];
        float part[8];
        #pragma unroll
        for (int cc = 0; cc < CPB; cc++) {
            const float* wp = &ws[cc * (CIN * 9) + j * 9];
            float w0 = wp[0], w1 = wp[1], w2 = wp[2];
            float w3 = wp[3], w4 = wp[4], w5 = wp[5];
            float w6 = wp[6], w7 = wp[7], w8 = wp[8];
            float sv2 = 0.f, sav = 0.f;
            #pragma unroll
            for (int i = 0; i < 8; i++) {
                float vv = u0[i] * w0 + u0[i + 1] * w1 + u0[i + 2] * w2
                         + u1[i] * w3 + u1[i + 1] * w4 + u1[i + 2] * w5
                         + u2[i] * w6 + u2[i + 1] * w7 + u2[i + 2] * w8;
                v[cc][i] = vv;
                sv2 += vv * vv;
                sav += acc[cc][i] * vv;
            }
            part[cc * 2]     = sv2;
            part[cc * 2 + 1] = sav;
        }

        // stage-1 reduce (warp level)
        #pragma unroll
        for (int q = 0; q < 8; q++) {
            #pragma unroll
            for (int o = 16; o; o >>= 1)
                part[q] += __shfl_xor_sync(0xffffffffu, part[q], o);
        }
        if (lane == 0) {
            #pragma unroll
            for (int q = 0; q < 8; q++) red[q][wid] = part[q];
        }

        // store prefetched tile into the other buffer (overlaps reduction window)
        if (j < CIN - 1) {
            float s = sc_s[j + 1];
            float* B = buf[(j + 1) & 1];
            *reinterpret_cast<float4*>(B + d0) =
                make_float4(pf0.x * s, pf0.y * s, pf0.z * s, pf0.w * s);
            *reinterpret_cast<float4*>(B + d1) =
                make_float4(pf1.x * s, pf1.y * s, pf1.z * s, pf1.w * s);
        }
        __syncthreads();

        // stage-2 reduce: warp q reduces scalar q (parallel across 8 warps)
        if (wid < 8) {
            float val = (lane < 16) ? red[wid][lane] : 0.f;
            #pragma unroll
            for (int o = 8; o; o >>= 1)
                val += __shfl_xor_sync(0xffffffffu, val, o);
            if (lane == 0) res[wid] = val;
        }
        __syncthreads();

        // mobius update per cout (scalar math is uniform across the block)
        #pragma unroll
        for (int cc = 0; cc < CPB; cc++) {
            float sv2 = res[cc * 2], sav = res[cc * 2 + 1];
            float nv  = sqrtf(sv2);
            float un  = fmaxf(nv, MINN);
            float th  = tanhf(SQC * un);
            float m   = fminf(th, 0.996f);           // fold project(t)
            float gam = m / (SQC * un);
            float y2  = gam * gam * sv2;
            float xy  = gam * sav;
            float Aa  = 1.f + 2.f * C_CURV * xy + C_CURV * y2;
            float Bb  = 1.f - C_CURV * x2[cc];
            float den = fmaxf(1.f + 2.f * C_CURV * xy
                              + C_CURV * C_CURV * x2[cc] * y2, MINN);
            float rden = 1.f / den;
            float n2 = (Aa * Aa * x2[cc] + 2.f * Aa * Bb * xy + Bb * Bb * y2) * rden * rden;
            float n  = fmaxf(sqrtf(n2), MINN);
            float ps = (n > MAXNORM) ? (MAXNORM / n) : 1.f;
            float ka = Aa * rden * ps;
            float kv = Bb * gam * rden * ps;
            #pragma unroll
            for (int i = 0; i < 8; i++)
                acc[cc][i] = ka * acc[cc][i] + kv * v[cc][i];
            float nn = fminf(n, MAXNORM);
            x2[cc] = nn * nn;
        }
    }

    // ---- bias step: y spatially constant -> only need sum(acc) ----
    {
        float part[8];
        #pragma unroll
        for (int cc = 0; cc < CPB; cc++) {
            float s = 0.f;
            #pragma unroll
            for (int i = 0; i < 8; i++) s += acc[cc][i];
            part[cc] = s;
        }
        #pragma unroll
        for (int cc = CPB; cc < 8; cc++) part[cc] = 0.f;

        #pragma unroll
        for (int q = 0; q < 8; q++) {
            #pragma unroll
            for (int o = 16; o; o >>= 1)
                part[q] += __shfl_xor_sync(0xffffffffu, part[q], o);
        }
        if (lane == 0) {
            #pragma unroll
            for (int q = 0; q < 8; q++) red[q][wid] = part[q];
        }
        __syncthreads();
        if (wid < 8) {
            float val = (lane < 16) ? red[wid][lane] : 0.f;
            #pragma unroll
            for (int o = 8; o; o >>= 1)
                val += __shfl_xor_sync(0xffffffffu, val, o);
            if (lane == 0) res[wid] = val;
        }
        __syncthreads();

        #pragma unroll
        for (int cc = 0; cc < CPB; cc++) {
            int co = cog * CPB + cc;
            float bh = g_bh[co];
            float sa = res[cc];
            float y2 = (float)NPIX * bh * bh;
            float xy = bh * sa;
            float Aa  = 1.f + 2.f * C_CURV * xy + C_CURV * y2;
            float Bb  = 1.f - C_CURV * x2[cc];
            float den = fmaxf(1.f + 2.f * C_CURV * xy
                              + C_CURV * C_CURV * x2[cc] * y2, MINN);
            float rden = 1.f / den;
            float n2 = (Aa * Aa * x2[cc] + 2.f * Aa * Bb * xy + Bb * Bb * y2) * rden * rden;
            float n  = fmaxf(sqrtf(n2), MINN);
            float ps = (n > MAXNORM) ? (MAXNORM / n) : 1.f;
            float ka = Aa * rden * ps;
            float kb = Bb * bh * rden * ps;

            float o4a[4], o4b[4];
            #pragma unroll
            for (int i = 0; i < 4; i++) o4a[i] = ka * acc[cc][i] + kb;
            #pragma unroll
            for (int i = 0; i < 4; i++) o4b[i] = ka * acc[cc][4 + i] + kb;

            float* op = out + (((size_t)b * COUT + co) * HW + r) * HW + cb;
            *reinterpret_cast<float4*>(op)     = make_float4(o4a[0], o4a[1], o4a[2], o4a[3]);
            *reinterpret_cast<float4*>(op + 4) = make_float4(o4b[0], o4b[1], o4b[2], o4b[3]);
        }
    }
}

// ---------------- launch ----------------
extern "C" void kernel_launch(void* const* d_in, const int* in_sizes, int n_in,
                              void* d_out, int out_size) {
    const float* x    = (const float*)d_in[0];
    const float* wgt  = (const float*)d_in[1];
    const float* bias = (const float*)d_in[2];
    float* out = (float*)d_out;

    scale_kernel<<<BS * CIN, 256>>>(x);
    bias_kernel<<<1, COUT>>>(bias);
    dim3 grid(COUT / CPB, BS);   // (32, 32)
    hypconv_kernel<<<grid, NT>>>(x, wgt, out);
}